// round 5
// baseline (speedup 1.0000x reference)
#include <cuda_runtime.h>
#include <cuda_bf16.h>
#include <cstdint>

// ---------------------------------------------------------------------------
// ArcFace loss on GB300 (sm_103a). mma.sync pipeline (tcgen05 rejected by the
// harness's compute_103 virtual target).
//   k_norm_x : normalize x rows fp32 -> bf16 (g_xn).
//   k_main   : grid (4 M-tiles x 782 chunks of 128 classes), 512 threads.
//              W fp32 LDG'd, converted to bf16 + sum-of-squares IN-KERNEL
//              (distance-2 register pipeline, 2-stage smem bf16 buffer).
//              X tile (128x512 bf16) smem-resident via cp.async.
//              32x32 warp tiles, ldmatrix.x4 + HMMA, fused exp(64*cos-64)
//              row sums (fixed-max LSE trick).
//   k_final  : combine partials, margin at target, CE, mean.
// ---------------------------------------------------------------------------

namespace {
constexpr int NUM_C = 100000;
constexpr int DIM   = 512;
constexpr int NB    = 512;

constexpr int NPC   = 128;                        // classes per CTA
constexpr int NCCH  = (NUM_C + NPC - 1) / NPC;    // 782

constexpr int SM_X  = 0;                 // 8 chunks * 16384 = 131072
constexpr int SM_WS = 131072;            // 2 stages * 16384 = 32768
constexpr size_t SMEM_BYTES = 163840;

constexpr float COS_M = 0.8775825618903728f;   // cos(0.5)
constexpr float SIN_M = 0.479425538604203f;    // sin(0.5)
constexpr float THv   = -0.8775825618903728f;  // -cos(m)
constexpr float MMRG  = 0.2397127693021015f;   // sin(m)*m
} // namespace

__device__ __align__(16) __nv_bfloat16 g_xn[NB * DIM];
__device__ float g_tgt[NB];
__device__ float g_partial[(size_t)NCCH * NB];

// ---------------------------------------------------------------------------
__device__ __forceinline__ uint32_t smem_u32(const void* p) {
    uint32_t a;
    asm("{ .reg .u64 t; cvta.to.shared.u64 t, %1; cvt.u32.u64 %0, t; }"
        : "=r"(a) : "l"(p));
    return a;
}
#define CP_ASYNC16(dst, src) \
    asm volatile("cp.async.cg.shared.global [%0], [%1], 16;" \
                 :: "r"(dst), "l"(src) : "memory")
#define CP_COMMIT() asm volatile("cp.async.commit_group;" ::: "memory")
#define CP_WAIT0()  asm volatile("cp.async.wait_group 0;" ::: "memory")

#define LDSM4(r, addr) \
    asm volatile("ldmatrix.sync.aligned.m8n8.x4.shared.b16 {%0,%1,%2,%3}, [%4];" \
                 : "=r"((r)[0]), "=r"((r)[1]), "=r"((r)[2]), "=r"((r)[3])        \
                 : "r"(addr))

__device__ __forceinline__ void mma16816(float* c, const uint32_t* a,
                                         const uint32_t* b) {
    asm volatile(
        "mma.sync.aligned.m16n8k16.row.col.f32.bf16.bf16.f32 "
        "{%0,%1,%2,%3}, {%4,%5,%6,%7}, {%8,%9}, {%0,%1,%2,%3};\n"
        : "+f"(c[0]), "+f"(c[1]), "+f"(c[2]), "+f"(c[3])
        : "r"(a[0]), "r"(a[1]), "r"(a[2]), "r"(a[3]), "r"(b[0]), "r"(b[1]));
}

// ---------------------------------------------------------------------------
__global__ void k_norm_x(const float* __restrict__ x) {
    int row  = blockIdx.x * 8 + (threadIdx.x >> 5);
    int lane = threadIdx.x & 31;
    const float4* xr = (const float4*)(x + (size_t)row * DIM);
    float4 v[4];
    float s = 0.f;
    #pragma unroll
    for (int j = 0; j < 4; ++j) {
        v[j] = xr[lane + 32 * j];
        s += v[j].x * v[j].x + v[j].y * v[j].y + v[j].z * v[j].z + v[j].w * v[j].w;
    }
    #pragma unroll
    for (int o = 16; o; o >>= 1) s += __shfl_xor_sync(0xFFFFFFFFu, s, o);
    float inv = rsqrtf(fmaxf(s, 1e-24f));
    uint2* dst = (uint2*)(g_xn + (size_t)row * DIM);
    #pragma unroll
    for (int j = 0; j < 4; ++j) {
        __nv_bfloat162 lo = __floats2bfloat162_rn(v[j].x * inv, v[j].y * inv);
        __nv_bfloat162 hi = __floats2bfloat162_rn(v[j].z * inv, v[j].w * inv);
        uint2 u;
        u.x = *(uint32_t*)&lo;
        u.y = *(uint32_t*)&hi;
        dst[lane + 32 * j] = u;
    }
}

// ---------------------------------------------------------------------------
__global__ void __launch_bounds__(512, 1)
k_main(const float* __restrict__ w, const int* __restrict__ y) {
    extern __shared__ char smem[];
    const uint32_t sb = smem_u32(smem);
    const int tid  = threadIdx.x;
    const int wid  = tid >> 5;
    const int lane = tid & 31;
    const int mt   = blockIdx.x;           // 0..3
    const int cch  = blockIdx.y;           // 0..781
    const int c0   = cch * NPC;
    const int wm   = wid >> 2;             // 0..3  (32-row slice)
    const int wn   = wid & 3;              // 0..3  (32-col slice)

    // ---- X tile resident (cp.async, 16 x 16B per thread) ----
    {
        const char* xsrc = (const char*)g_xn + (size_t)mt * 128 * DIM * 2;
        #pragma unroll
        for (int i = 0; i < 16; ++i) {
            int li  = tid + 512 * i;
            int c   = li >> 10, lc = li & 1023;
            int row = lc >> 3, seg = lc & 7;
            uint32_t dst = sb + SM_X + c * 16384 + row * 128
                         + ((seg * 16) ^ ((row & 7) << 4));
            const char* src = xsrc + ((size_t)row * DIM + c * 64 + seg * 8) * 2;
            CP_ASYNC16(dst, src);
        }
        CP_COMMIT();
    }

    // ---- W producer setup: thread owns (cls[it], q) for it=0..3 ----
    const int q     = tid & 15;            // float4 index within 64-elem chunk row
    const int chi   = tid >> 4;            // 0..31
    int   cls[4];
    bool  ok[4];
    const float* gp[4];
    uint32_t stso[4];
    #pragma unroll
    for (int it = 0; it < 4; ++it) {
        cls[it]  = it * 32 + chi;
        ok[it]   = (c0 + cls[it]) < NUM_C;
        gp[it]   = w + (size_t)(c0 + cls[it]) * DIM + q * 4;
        stso[it] = (uint32_t)(cls[it] * 128 + ((q * 8) ^ ((cls[it] & 7) << 4)));
    }
    float part[4] = {0.f, 0.f, 0.f, 0.f};

    float4 rA[2], rB[2];
    #define LDG_HALF(r, i0, kc) do {                                          \
        _Pragma("unroll")                                                     \
        for (int u = 0; u < 2; ++u) {                                         \
            int it = (i0) + u;                                                \
            r[u] = ok[it] ? *(const float4*)(gp[it] + (kc) * 64)              \
                          : make_float4(0.f, 0.f, 0.f, 0.f);                  \
        }                                                                     \
    } while (0)
    #define CVT_HALF(r, i0, bufb) do {                                        \
        _Pragma("unroll")                                                     \
        for (int u = 0; u < 2; ++u) {                                         \
            int it = (i0) + u;                                                \
            float4 v = r[u];                                                  \
            part[it] += v.x * v.x + v.y * v.y + v.z * v.z + v.w * v.w;        \
            __nv_bfloat162 p0 = __floats2bfloat162_rn(v.x, v.y);              \
            __nv_bfloat162 p1 = __floats2bfloat162_rn(v.z, v.w);              \
            uint2 pk = { *(uint32_t*)&p0, *(uint32_t*)&p1 };                  \
            *(uint2*)(smem + (bufb) + stso[it]) = pk;                         \
        }                                                                     \
    } while (0)

    // prologue: chunk0 -> buf0; chunk1 -> regs
    LDG_HALF(rA, 0, 0); LDG_HALF(rB, 2, 0);
    CVT_HALF(rA, 0, SM_WS); CVT_HALF(rB, 2, SM_WS);
    LDG_HALF(rA, 0, 1); LDG_HALF(rB, 2, 1);
    CP_WAIT0();
    __syncthreads();

    float acc[2][4][4];
    #pragma unroll
    for (int mi = 0; mi < 2; ++mi)
        #pragma unroll
        for (int ni = 0; ni < 4; ++ni)
            #pragma unroll
            for (int j = 0; j < 4; ++j) acc[mi][ni][j] = 0.f;

    const uint32_t swz      = (lane & 7) << 4;
    const uint32_t xrowbase = (wm * 32 + (lane & 15)) * 128;
    const uint32_t kxA      = (lane >> 4) << 4;
    const uint32_t browbase = (wn * 32 + (lane & 7) + ((lane >> 4) << 3)) * 128;
    const uint32_t kxB      = ((lane >> 3) & 1) << 4;

    for (int kc = 0; kc < 8; ++kc) {
        const uint32_t bufw = SM_WS + (((kc + 1) & 1) << 14);
        if (kc < 7) CVT_HALF(rA, 0, bufw);
        if (kc < 6) LDG_HALF(rA, 0, kc + 2);

        const uint32_t xch = sb + SM_X + kc * 16384 + xrowbase;
        const uint32_t wst = sb + SM_WS + ((kc & 1) << 14) + browbase;
        #pragma unroll
        for (int ks = 0; ks < 4; ++ks) {
            uint32_t a[2][4], bq[2][4];
            const uint32_t ka = (uint32_t)(ks * 32 + kxA) ^ swz;
            const uint32_t kb = (uint32_t)(ks * 32 + kxB) ^ swz;
            #pragma unroll
            for (int mi = 0; mi < 2; ++mi) LDSM4(a[mi], xch + mi * 2048 + ka);
            #pragma unroll
            for (int nb = 0; nb < 2; ++nb) LDSM4(bq[nb], wst + nb * 2048 + kb);
            #pragma unroll
            for (int mi = 0; mi < 2; ++mi)
                #pragma unroll
                for (int nb = 0; nb < 2; ++nb) {
                    mma16816(acc[mi][2 * nb],     a[mi], &bq[nb][0]);
                    mma16816(acc[mi][2 * nb + 1], a[mi], &bq[nb][2]);
                }
        }

        if (kc < 7) CVT_HALF(rB, 2, bufw);
        if (kc < 6) LDG_HALF(rB, 2, kc + 2);
        __syncthreads();
    }

    // ---- winv from per-thread partials (16-lane groups share a class) ----
    float* winv_s = (float*)(smem + SM_WS);
    #pragma unroll
    for (int it = 0; it < 4; ++it) {
        float v = part[it];
        v += __shfl_xor_sync(0xFFFFFFFFu, v, 1);
        v += __shfl_xor_sync(0xFFFFFFFFu, v, 2);
        v += __shfl_xor_sync(0xFFFFFFFFu, v, 4);
        v += __shfl_xor_sync(0xFFFFFFFFu, v, 8);
        if ((lane & 15) == 0)
            winv_s[cls[it]] = ok[it] ? rsqrtf(fmaxf(v, 1e-24f)) : 0.f;
    }
    __syncthreads();

    // ---- epilogue: cos = acc * winv; rowsum exp(64*cos - 64) ----
    float* racc = (float*)(smem + SM_WS + 512);
    const int qq = lane & 3;
    const int g8 = lane >> 2;

    float2 wv[4];
    #pragma unroll
    for (int ni = 0; ni < 4; ++ni)
        wv[ni] = *(const float2*)&winv_s[wn * 32 + ni * 8 + 2 * qq];

    #pragma unroll
    for (int mi = 0; mi < 2; ++mi) {
        #pragma unroll
        for (int h = 0; h < 2; ++h) {
            const int lrow = wm * 32 + mi * 16 + g8 + 8 * h;
            const int grow = mt * 128 + lrow;
            const int yv   = y[grow];
            float rs = 0.f;
            #pragma unroll
            for (int ni = 0; ni < 4; ++ni) {
                const int cb = c0 + wn * 32 + ni * 8 + 2 * qq;
                float cv0 = acc[mi][ni][2 * h + 0] * wv[ni].x;
                float cv1 = acc[mi][ni][2 * h + 1] * wv[ni].y;
                if (cb == yv)     g_tgt[grow] = cv0;
                if (cb + 1 == yv) g_tgt[grow] = cv1;
                float e0 = __expf(fmaf(cv0, 64.f, -64.f));
                float e1 = __expf(fmaf(cv1, 64.f, -64.f));
                if (cb < NUM_C)     rs += e0;
                if (cb + 1 < NUM_C) rs += e1;
            }
            rs += __shfl_xor_sync(0xFFFFFFFFu, rs, 1);
            rs += __shfl_xor_sync(0xFFFFFFFFu, rs, 2);
            if (qq == 0) racc[lrow * 4 + wn] = rs;
        }
    }
    __syncthreads();
    if (tid < 128) {
        float s = racc[tid * 4 + 0] + racc[tid * 4 + 1]
                + racc[tid * 4 + 2] + racc[tid * 4 + 3];
        g_partial[(size_t)cch * NB + mt * 128 + tid] = s;
    }
    #undef LDG_HALF
    #undef CVT_HALF
}

// ---------------------------------------------------------------------------
__global__ void k_final(float* __restrict__ out) {
    __shared__ float part[1024];
    __shared__ float red[NB];
    const int t    = threadIdx.x;
    const int row  = t >> 1;
    const int half = t & 1;
    const int cb   = half ? 391 : 0;
    const int ce   = half ? NCCH : 391;

    float s = 0.f;
    int c = cb;
    #pragma unroll 8
    for (; c + 8 <= ce; c += 8) {
        float a0 = g_partial[(size_t)(c + 0) * NB + row];
        float a1 = g_partial[(size_t)(c + 1) * NB + row];
        float a2 = g_partial[(size_t)(c + 2) * NB + row];
        float a3 = g_partial[(size_t)(c + 3) * NB + row];
        float a4 = g_partial[(size_t)(c + 4) * NB + row];
        float a5 = g_partial[(size_t)(c + 5) * NB + row];
        float a6 = g_partial[(size_t)(c + 6) * NB + row];
        float a7 = g_partial[(size_t)(c + 7) * NB + row];
        s += ((a0 + a1) + (a2 + a3)) + ((a4 + a5) + (a6 + a7));
    }
    for (; c < ce; ++c) s += g_partial[(size_t)c * NB + row];
    part[t] = s;
    __syncthreads();

    if (t < NB) {
        float S = part[2 * t] + part[2 * t + 1];
        float ct  = g_tgt[t];
        float sn  = sqrtf(fmaxf(1.f - ct * ct, 0.f));
        float cwm = ct * COS_M - sn * SIN_M;
        float phi = (ct > THv) ? cwm : (ct - MMRG);
        float Sp  = S - __expf(fmaf(ct, 64.f, -64.f)) + __expf(fmaf(phi, 64.f, -64.f));
        red[t] = 64.f + logf(Sp) - 64.f * phi;
    }
    __syncthreads();
    #pragma unroll
    for (int st = 256; st; st >>= 1) {
        if (t < st) red[t] += red[t + st];
        __syncthreads();
    }
    if (t == 0) out[0] = red[0] / (float)NB;
}

// ---------------------------------------------------------------------------
extern "C" void kernel_launch(void* const* d_in, const int* in_sizes, int n_in,
                              void* d_out, int out_size) {
    const float* x = (const float*)d_in[0];
    const int*   y = (const int*)d_in[1];
    const float* w = (const float*)d_in[2];
    float* out = (float*)d_out;

    cudaFuncSetAttribute(k_main, cudaFuncAttributeMaxDynamicSharedMemorySize,
                         (int)SMEM_BYTES);

    k_norm_x<<<64, 256>>>(x);
    k_main<<<dim3(4, NCCH), 512, SMEM_BYTES>>>(w, y);
    k_final<<<1, 1024>>>(out);
}

// round 6
// speedup vs baseline: 1.1820x; 1.1820x over previous
#include <cuda_runtime.h>
#include <cuda_bf16.h>
#include <cstdint>

// ---------------------------------------------------------------------------
// ArcFace loss on GB300 (sm_103a). mma.sync pipeline (tcgen05 rejected by the
// harness's compute_103 virtual target).
//   k_prep   : W fp32 -> bf16 (g_wn) + inv-norms (g_winv); X normalized bf16.
//   k_main   : 1564 CTAs (4 M-tiles x 391 chunks of 256 classes), 512 thr.
//              X tile smem-resident (cp.async); W bf16 3-stage cp.async
//              pipeline with ONE barrier per k-chunk (issue-before-consume,
//              depth 2); 64x32 warp tiles, ldmatrix.x4 + HMMA; fused
//              exp(64*cos-64) row sums (fixed-max LSE trick).
//   k_final1 : per-row combine of 391 partials + margin + nll (512 blocks).
//   k_final2 : mean over 512 rows.
// ---------------------------------------------------------------------------

namespace {
constexpr int NUM_C = 100000;
constexpr int DIM   = 512;
constexpr int NB    = 512;

constexpr int NPC   = 256;                        // classes per CTA
constexpr int NCCH  = (NUM_C + NPC - 1) / NPC;    // 391
constexpr int NCHP  = 392;                        // padded partial stride
constexpr int CPAD  = NCCH * NPC;                 // 100096

constexpr int SM_X  = 0;                // 8 chunks * 16384 = 131072
constexpr int SM_W  = 131072;           // 3 stages * 32768 = 98304
constexpr size_t SMEM_BYTES = 229376;

constexpr float COS_M = 0.8775825618903728f;   // cos(0.5)
constexpr float SIN_M = 0.479425538604203f;    // sin(0.5)
constexpr float THv   = -0.8775825618903728f;  // -cos(m)
constexpr float MMRG  = 0.2397127693021015f;   // sin(m)*m
} // namespace

__device__ __align__(16) __nv_bfloat16 g_xn[NB * DIM];
__device__ __align__(16) __nv_bfloat16 g_wn[(size_t)CPAD * DIM];
__device__ float g_winv[CPAD];
__device__ float g_tgt[NB];
__device__ float g_partial[(size_t)NB * NCHP];   // [row][chunk]
__device__ float g_nll[NB];

// ---------------------------------------------------------------------------
__device__ __forceinline__ uint32_t smem_u32(const void* p) {
    uint32_t a;
    asm("{ .reg .u64 t; cvta.to.shared.u64 t, %1; cvt.u32.u64 %0, t; }"
        : "=r"(a) : "l"(p));
    return a;
}
#define CP_ASYNC16(dst, src) \
    asm volatile("cp.async.cg.shared.global [%0], [%1], 16;" \
                 :: "r"(dst), "l"(src) : "memory")
#define CP_COMMIT() asm volatile("cp.async.commit_group;" ::: "memory")
#define CP_WAIT1()  asm volatile("cp.async.wait_group 1;" ::: "memory")

#define LDSM4(r, addr) \
    asm volatile("ldmatrix.sync.aligned.m8n8.x4.shared.b16 {%0,%1,%2,%3}, [%4];" \
                 : "=r"((r)[0]), "=r"((r)[1]), "=r"((r)[2]), "=r"((r)[3])        \
                 : "r"(addr))

__device__ __forceinline__ void mma16816(float* c, const uint32_t* a,
                                         const uint32_t* b) {
    asm volatile(
        "mma.sync.aligned.m16n8k16.row.col.f32.bf16.bf16.f32 "
        "{%0,%1,%2,%3}, {%4,%5,%6,%7}, {%8,%9}, {%0,%1,%2,%3};\n"
        : "+f"(c[0]), "+f"(c[1]), "+f"(c[2]), "+f"(c[3])
        : "r"(a[0]), "r"(a[1]), "r"(a[2]), "r"(a[3]), "r"(b[0]), "r"(b[1]));
}

// ---------------------------------------------------------------------------
// Prep: blocks 0..1563 convert 64 W rows each (zero-pad past NUM_C);
//       blocks 1564..1565 normalize 256 X rows each.
// ---------------------------------------------------------------------------
__global__ void k_prep(const float* __restrict__ x, const float* __restrict__ w) {
    const int bid  = blockIdx.x;
    const int wid  = threadIdx.x >> 5;
    const int lane = threadIdx.x & 31;

    if (bid < CPAD / 64) {
        const int base = bid * 64 + wid * 8;
        #pragma unroll
        for (int r = 0; r < 8; ++r) {
            const int row = base + r;
            float4 a0, a1, a2, a3;
            float ss = 0.f;
            if (row < NUM_C) {
                const float4* src = (const float4*)(w + (size_t)row * DIM);
                a0 = src[2 * lane];
                a1 = src[2 * lane + 1];
                a2 = src[2 * lane + 64];
                a3 = src[2 * lane + 65];
                ss = a0.x * a0.x + a0.y * a0.y + a0.z * a0.z + a0.w * a0.w
                   + a1.x * a1.x + a1.y * a1.y + a1.z * a1.z + a1.w * a1.w
                   + a2.x * a2.x + a2.y * a2.y + a2.z * a2.z + a2.w * a2.w
                   + a3.x * a3.x + a3.y * a3.y + a3.z * a3.z + a3.w * a3.w;
            } else {
                a0 = a1 = a2 = a3 = make_float4(0.f, 0.f, 0.f, 0.f);
            }
            #pragma unroll
            for (int o = 16; o; o >>= 1) ss += __shfl_xor_sync(0xFFFFFFFFu, ss, o);

            uint4* dst = (uint4*)(g_wn + (size_t)row * DIM);
            {
                __nv_bfloat162 p0 = __floats2bfloat162_rn(a0.x, a0.y);
                __nv_bfloat162 p1 = __floats2bfloat162_rn(a0.z, a0.w);
                __nv_bfloat162 p2 = __floats2bfloat162_rn(a1.x, a1.y);
                __nv_bfloat162 p3 = __floats2bfloat162_rn(a1.z, a1.w);
                uint4 u = { *(uint32_t*)&p0, *(uint32_t*)&p1,
                            *(uint32_t*)&p2, *(uint32_t*)&p3 };
                dst[lane] = u;
            }
            {
                __nv_bfloat162 p0 = __floats2bfloat162_rn(a2.x, a2.y);
                __nv_bfloat162 p1 = __floats2bfloat162_rn(a2.z, a2.w);
                __nv_bfloat162 p2 = __floats2bfloat162_rn(a3.x, a3.y);
                __nv_bfloat162 p3 = __floats2bfloat162_rn(a3.z, a3.w);
                uint4 u = { *(uint32_t*)&p0, *(uint32_t*)&p1,
                            *(uint32_t*)&p2, *(uint32_t*)&p3 };
                dst[lane + 32] = u;
            }
            if (lane == 0)
                g_winv[row] = (row < NUM_C) ? rsqrtf(fmaxf(ss, 1e-24f)) : 0.f;
        }
    } else {
        const int xb = (bid - CPAD / 64) * 256 + wid * 32;
        for (int r = 0; r < 32; ++r) {
            const int row = xb + r;
            const float4* xr = (const float4*)(x + (size_t)row * DIM);
            float4 v[4];
            float s = 0.f;
            #pragma unroll
            for (int j = 0; j < 4; ++j) {
                v[j] = xr[lane + 32 * j];
                s += v[j].x * v[j].x + v[j].y * v[j].y
                   + v[j].z * v[j].z + v[j].w * v[j].w;
            }
            #pragma unroll
            for (int o = 16; o; o >>= 1) s += __shfl_xor_sync(0xFFFFFFFFu, s, o);
            float inv = rsqrtf(fmaxf(s, 1e-24f));
            uint2* dst = (uint2*)(g_xn + (size_t)row * DIM);
            #pragma unroll
            for (int j = 0; j < 4; ++j) {
                __nv_bfloat162 lo = __floats2bfloat162_rn(v[j].x * inv, v[j].y * inv);
                __nv_bfloat162 hi = __floats2bfloat162_rn(v[j].z * inv, v[j].w * inv);
                uint2 u;
                u.x = *(uint32_t*)&lo;
                u.y = *(uint32_t*)&hi;
                dst[lane + 32 * j] = u;
            }
        }
    }
}

// ---------------------------------------------------------------------------
__global__ void __launch_bounds__(512, 1)
k_main(const int* __restrict__ y) {
    extern __shared__ char smem[];
    const uint32_t sb = smem_u32(smem);
    const int tid  = threadIdx.x;
    const int wid  = tid >> 5;
    const int lane = tid & 31;
    const int mt   = blockIdx.x;           // 0..3
    const int cch  = blockIdx.y;           // 0..390
    const int c0   = cch * NPC;
    const int wm   = wid >> 3;             // 0..1  (64-row half)
    const int wn   = wid & 7;              // 0..7  (32-col slice)

    // ---- prologue: X tile (group 0) + W chunks 0,1 (groups 1,2) ----
    {
        const char* xsrc = (const char*)g_xn + (size_t)mt * 128 * DIM * 2;
        #pragma unroll
        for (int i = 0; i < 16; ++i) {
            int li  = tid + 512 * i;
            int c   = li >> 10, lc = li & 1023;
            int row = lc >> 3, seg = lc & 7;
            uint32_t dst = sb + SM_X + c * 16384 + row * 128
                         + ((seg * 16) ^ ((row & 7) << 4));
            const char* src = xsrc + ((size_t)row * DIM + c * 64 + seg * 8) * 2;
            CP_ASYNC16(dst, src);
        }
        CP_COMMIT();
    }
    const char* wbase = (const char*)g_wn + (size_t)c0 * DIM * 2;
    #define ISSUE_W(kc) do {                                                  \
        uint32_t stg = sb + SM_W + ((kc) % 3) * 32768;                        \
        _Pragma("unroll")                                                     \
        for (int i = 0; i < 4; ++i) {                                         \
            int li = tid + 512 * i;                                           \
            int row = li >> 3, seg = li & 7;                                  \
            uint32_t dst = stg + row * 128 + ((seg * 16) ^ ((row & 7) << 4)); \
            const char* src = wbase + ((size_t)row * DIM + (kc) * 64 + seg * 8) * 2; \
            CP_ASYNC16(dst, src);                                             \
        }                                                                     \
    } while (0)

    ISSUE_W(0); CP_COMMIT();
    ISSUE_W(1); CP_COMMIT();

    float acc[4][4][4];
    #pragma unroll
    for (int mi = 0; mi < 4; ++mi)
        #pragma unroll
        for (int ni = 0; ni < 4; ++ni)
            #pragma unroll
            for (int j = 0; j < 4; ++j) acc[mi][ni][j] = 0.f;

    const uint32_t swz      = (lane & 7) << 4;
    const uint32_t xrowbase = (wm * 64 + (lane & 15)) * 128;
    const uint32_t kxA      = (lane >> 4) << 4;
    const uint32_t browbase = (wn * 32 + (lane & 7) + ((lane >> 4) << 3)) * 128;
    const uint32_t kxB      = ((lane >> 3) & 1) << 4;

    // single barrier per chunk: wait depth-1, sync, issue kc+2 into the stage
    // consumed at kc-1 (guarded by this barrier), then consume stage kc%3.
    for (int kc = 0; kc < 8; ++kc) {
        CP_WAIT1();
        __syncthreads();
        if (kc < 6) ISSUE_W(kc + 2);
        CP_COMMIT();

        const uint32_t xch = sb + SM_X + kc * 16384 + xrowbase;
        const uint32_t wst = sb + SM_W + (kc % 3) * 32768 + browbase;
        #pragma unroll
        for (int ks = 0; ks < 4; ++ks) {
            uint32_t a[4][4], bq[2][4];
            const uint32_t ka = (uint32_t)(ks * 32 + kxA) ^ swz;
            const uint32_t kb = (uint32_t)(ks * 32 + kxB) ^ swz;
            #pragma unroll
            for (int mi = 0; mi < 4; ++mi) LDSM4(a[mi], xch + mi * 2048 + ka);
            #pragma unroll
            for (int nb = 0; nb < 2; ++nb) LDSM4(bq[nb], wst + nb * 2048 + kb);
            #pragma unroll
            for (int mi = 0; mi < 4; ++mi)
                #pragma unroll
                for (int nb = 0; nb < 2; ++nb) {
                    mma16816(acc[mi][2 * nb],     a[mi], &bq[nb][0]);
                    mma16816(acc[mi][2 * nb + 1], a[mi], &bq[nb][2]);
                }
        }
    }

    // ---- epilogue: cos = acc * winv; rowsum exp(64*cos - 64) ----
    // racc lives in W stage 0 (last consumed at kc=6; all warps are past the
    // kc=7 top barrier, and kc=7 consumes stage 1 -> no overlap).
    float* racc = (float*)(smem + SM_W);
    const int q  = lane & 3;
    const int g8 = lane >> 2;

    float2 wv[4];
    #pragma unroll
    for (int ni = 0; ni < 4; ++ni)
        wv[ni] = *(const float2*)&g_winv[c0 + wn * 32 + ni * 8 + 2 * q];

    #pragma unroll
    for (int mi = 0; mi < 4; ++mi) {
        #pragma unroll
        for (int h = 0; h < 2; ++h) {
            const int lrow = wm * 64 + mi * 16 + g8 + 8 * h;
            const int grow = mt * 128 + lrow;
            const int yv   = y[grow];
            float rs = 0.f;
            #pragma unroll
            for (int ni = 0; ni < 4; ++ni) {
                const int cb = c0 + wn * 32 + ni * 8 + 2 * q;
                float cv0 = acc[mi][ni][2 * h + 0] * wv[ni].x;
                float cv1 = acc[mi][ni][2 * h + 1] * wv[ni].y;
                if (cb == yv)     g_tgt[grow] = cv0;
                if (cb + 1 == yv) g_tgt[grow] = cv1;
                float e0 = __expf(fmaf(cv0, 64.f, -64.f));
                float e1 = __expf(fmaf(cv1, 64.f, -64.f));
                if (cb < NUM_C)     rs += e0;
                if (cb + 1 < NUM_C) rs += e1;
            }
            rs += __shfl_xor_sync(0xFFFFFFFFu, rs, 1);
            rs += __shfl_xor_sync(0xFFFFFFFFu, rs, 2);
            if (q == 0) racc[lrow * 8 + wn] = rs;
        }
    }
    __syncthreads();
    if (tid < 128) {
        float s = 0.f;
        #pragma unroll
        for (int k = 0; k < 8; ++k) s += racc[tid * 8 + k];
        g_partial[(size_t)(mt * 128 + tid) * NCHP + cch] = s;
    }
    #undef ISSUE_W
}

// ---------------------------------------------------------------------------
// k_final1: one block per row — coalesced sum of 391 partials + margin + nll.
__global__ void k_final1(float* __restrict__ nll_out) {
    __shared__ float red[8];
    const int row = blockIdx.x;
    const int t   = threadIdx.x;
    float s = 0.f;
    for (int c = t; c < NCCH; c += 256)
        s += g_partial[(size_t)row * NCHP + c];
    #pragma unroll
    for (int o = 16; o; o >>= 1) s += __shfl_xor_sync(0xFFFFFFFFu, s, o);
    if ((t & 31) == 0) red[t >> 5] = s;
    __syncthreads();
    if (t == 0) {
        float S = 0.f;
        #pragma unroll
        for (int k = 0; k < 8; ++k) S += red[k];
        float ct  = g_tgt[row];
        float sn  = sqrtf(fmaxf(1.f - ct * ct, 0.f));
        float cwm = ct * COS_M - sn * SIN_M;
        float phi = (ct > THv) ? cwm : (ct - MMRG);
        float Sp  = S - __expf(fmaf(ct, 64.f, -64.f)) + __expf(fmaf(phi, 64.f, -64.f));
        nll_out[row] = 64.f + logf(Sp) - 64.f * phi;
    }
}

__global__ void k_final2(float* __restrict__ out) {
    __shared__ float red[NB];
    const int t = threadIdx.x;
    red[t] = g_nll[t];
    __syncthreads();
    #pragma unroll
    for (int st = 256; st; st >>= 1) {
        if (t < st) red[t] += red[t + st];
        __syncthreads();
    }
    if (t == 0) out[0] = red[0] / (float)NB;
}

// ---------------------------------------------------------------------------
extern "C" void kernel_launch(void* const* d_in, const int* in_sizes, int n_in,
                              void* d_out, int out_size) {
    const float* x = (const float*)d_in[0];
    const int*   y = (const int*)d_in[1];
    const float* w = (const float*)d_in[2];
    float* out = (float*)d_out;

    cudaFuncSetAttribute(k_main, cudaFuncAttributeMaxDynamicSharedMemorySize,
                         (int)SMEM_BYTES);

    float* d_nll;
    cudaGetSymbolAddress((void**)&d_nll, g_nll);

    k_prep<<<CPAD / 64 + 2, 256>>>(x, w);
    k_main<<<dim3(4, NCCH), 512, SMEM_BYTES>>>(y);
    k_final1<<<NB, 256>>>(d_nll);
    k_final2<<<1, NB>>>(out);
}

// round 7
// speedup vs baseline: 1.2822x; 1.0847x over previous
#include <cuda_runtime.h>
#include <cuda_bf16.h>
#include <cstdint>

// ---------------------------------------------------------------------------
// ArcFace loss on GB300 (sm_103a). mma.sync pipeline (tcgen05 rejected by the
// harness's compute_103 virtual target).
//   k_norm_x : normalize x rows fp32 -> bf16 (g_xn).
//   k_main   : grid (2 M-tiles x 782 chunks of 128 classes), 512 threads.
//              X streamed via 3-slot cp.async pipeline (32KB stages);
//              W fp32 LDG'd ONCE per (CTA,chunk), converted to bf16 +
//              sum-of-squares in-register (distance-1 pipeline) into a
//              2-buffer smem tile. 64x32 warp tiles, ldmatrix.x4 + HMMA,
//              fused exp(64*cos-64) row sums (fixed-max LSE trick).
//   k_final1 : per-row combine of 782 partials + margin + nll (512 blocks).
//   k_final2 : mean over 512 rows.
// ---------------------------------------------------------------------------

namespace {
constexpr int NUM_C = 100000;
constexpr int DIM   = 512;
constexpr int NB    = 512;

constexpr int NPC   = 128;                        // classes per CTA
constexpr int NCCH  = (NUM_C + NPC - 1) / NPC;    // 782
constexpr int NCHP  = 784;                        // padded partial stride

constexpr int SM_X  = 0;                 // 3 stages * 32768 = 98304
constexpr int SM_W  = 98304;             // 2 bufs   * 16384 = 32768
constexpr int SM_WI = 98304 + 16384;     // winv overlays W buf1 (post-loop)
constexpr size_t SMEM_BYTES = 131072;

constexpr float COS_M = 0.8775825618903728f;   // cos(0.5)
constexpr float SIN_M = 0.479425538604203f;    // sin(0.5)
constexpr float THv   = -0.8775825618903728f;  // -cos(m)
constexpr float MMRG  = 0.2397127693021015f;   // sin(m)*m
} // namespace

__device__ __align__(16) __nv_bfloat16 g_xn[NB * DIM];
__device__ float g_tgt[NB];
__device__ float g_partial[(size_t)NB * NCHP];   // [row][chunk]
__device__ float g_nll[NB];

// ---------------------------------------------------------------------------
__device__ __forceinline__ uint32_t smem_u32(const void* p) {
    uint32_t a;
    asm("{ .reg .u64 t; cvta.to.shared.u64 t, %1; cvt.u32.u64 %0, t; }"
        : "=r"(a) : "l"(p));
    return a;
}
#define CP_ASYNC16(dst, src) \
    asm volatile("cp.async.cg.shared.global [%0], [%1], 16;" \
                 :: "r"(dst), "l"(src) : "memory")
#define CP_COMMIT() asm volatile("cp.async.commit_group;" ::: "memory")
#define CP_WAIT1()  asm volatile("cp.async.wait_group 1;" ::: "memory")

#define LDSM4(r, addr) \
    asm volatile("ldmatrix.sync.aligned.m8n8.x4.shared.b16 {%0,%1,%2,%3}, [%4];" \
                 : "=r"((r)[0]), "=r"((r)[1]), "=r"((r)[2]), "=r"((r)[3])        \
                 : "r"(addr))

__device__ __forceinline__ void mma16816(float* c, const uint32_t* a,
                                         const uint32_t* b) {
    asm volatile(
        "mma.sync.aligned.m16n8k16.row.col.f32.bf16.bf16.f32 "
        "{%0,%1,%2,%3}, {%4,%5,%6,%7}, {%8,%9}, {%0,%1,%2,%3};\n"
        : "+f"(c[0]), "+f"(c[1]), "+f"(c[2]), "+f"(c[3])
        : "r"(a[0]), "r"(a[1]), "r"(a[2]), "r"(a[3]), "r"(b[0]), "r"(b[1]));
}

// ---------------------------------------------------------------------------
__global__ void k_norm_x(const float* __restrict__ x) {
    int row  = blockIdx.x * 8 + (threadIdx.x >> 5);
    int lane = threadIdx.x & 31;
    const float4* xr = (const float4*)(x + (size_t)row * DIM);
    float4 v[4];
    float s = 0.f;
    #pragma unroll
    for (int j = 0; j < 4; ++j) {
        v[j] = xr[lane + 32 * j];
        s += v[j].x * v[j].x + v[j].y * v[j].y + v[j].z * v[j].z + v[j].w * v[j].w;
    }
    #pragma unroll
    for (int o = 16; o; o >>= 1) s += __shfl_xor_sync(0xFFFFFFFFu, s, o);
    float inv = rsqrtf(fmaxf(s, 1e-24f));
    uint2* dst = (uint2*)(g_xn + (size_t)row * DIM);
    #pragma unroll
    for (int j = 0; j < 4; ++j) {
        __nv_bfloat162 lo = __floats2bfloat162_rn(v[j].x * inv, v[j].y * inv);
        __nv_bfloat162 hi = __floats2bfloat162_rn(v[j].z * inv, v[j].w * inv);
        uint2 u;
        u.x = *(uint32_t*)&lo;
        u.y = *(uint32_t*)&hi;
        dst[lane + 32 * j] = u;
    }
}

// ---------------------------------------------------------------------------
__global__ void __launch_bounds__(512, 1)
k_main(const float* __restrict__ w, const int* __restrict__ y) {
    extern __shared__ char smem[];
    const uint32_t sb = smem_u32(smem);
    const int tid  = threadIdx.x;
    const int wid  = tid >> 5;
    const int lane = tid & 31;
    const int mt   = blockIdx.x;           // 0..1 (256-row half)
    const int cch  = blockIdx.y;           // 0..781
    const int c0   = cch * NPC;
    const int wm   = wid >> 2;             // 0..3  (64-row slice)
    const int wn   = wid & 3;              // 0..3  (32-col slice)

    const char* xsrc = (const char*)g_xn + (size_t)mt * 256 * DIM * 2;
    // X stage: 256 rows x 64 cols bf16 = 32KB; thread writes 4x16B.
    #define ISSUE_X(kc) do {                                                  \
        uint32_t stg = sb + SM_X + ((kc) % 3) * 32768;                        \
        _Pragma("unroll")                                                     \
        for (int i = 0; i < 4; ++i) {                                         \
            int li = tid + 512 * i;                                           \
            int row = li >> 3, seg = li & 7;                                  \
            uint32_t dst = stg + row * 128 + ((seg * 16) ^ ((row & 7) << 4)); \
            const char* src = xsrc + ((size_t)row * DIM + (kc) * 64 + seg * 8) * 2; \
            CP_ASYNC16(dst, src);                                             \
        }                                                                     \
    } while (0)

    // W producer: thread owns class wc = tid>>2, k-quarter q = tid&3 (16 floats)
    const int  wc  = tid >> 2;
    const int  q   = tid & 3;
    const bool ok  = (c0 + wc) < NUM_C;
    const float* gp = w + (size_t)(c0 + wc) * DIM + q * 16;
    const uint32_t sts0 = (uint32_t)(wc * 128 + ((q * 32)      ^ ((wc & 7) << 4)));
    const uint32_t sts1 = (uint32_t)(wc * 128 + ((q * 32 + 16) ^ ((wc & 7) << 4)));
    float ss = 0.f;
    float4 wr0, wr1, wr2, wr3;

    #define LDG_W(kc) do {                                                    \
        const float4* p = (const float4*)(gp + (kc) * 64);                    \
        if (ok) { wr0 = p[0]; wr1 = p[1]; wr2 = p[2]; wr3 = p[3]; }           \
        else { wr0 = wr1 = wr2 = wr3 = make_float4(0.f, 0.f, 0.f, 0.f); }     \
    } while (0)
    #define CVT_W(bufb) do {                                                  \
        ss += wr0.x * wr0.x + wr0.y * wr0.y + wr0.z * wr0.z + wr0.w * wr0.w   \
            + wr1.x * wr1.x + wr1.y * wr1.y + wr1.z * wr1.z + wr1.w * wr1.w   \
            + wr2.x * wr2.x + wr2.y * wr2.y + wr2.z * wr2.z + wr2.w * wr2.w   \
            + wr3.x * wr3.x + wr3.y * wr3.y + wr3.z * wr3.z + wr3.w * wr3.w;  \
        __nv_bfloat162 a0 = __floats2bfloat162_rn(wr0.x, wr0.y);              \
        __nv_bfloat162 a1 = __floats2bfloat162_rn(wr0.z, wr0.w);              \
        __nv_bfloat162 a2 = __floats2bfloat162_rn(wr1.x, wr1.y);              \
        __nv_bfloat162 a3 = __floats2bfloat162_rn(wr1.z, wr1.w);              \
        __nv_bfloat162 b0 = __floats2bfloat162_rn(wr2.x, wr2.y);              \
        __nv_bfloat162 b1 = __floats2bfloat162_rn(wr2.z, wr2.w);              \
        __nv_bfloat162 b2 = __floats2bfloat162_rn(wr3.x, wr3.y);              \
        __nv_bfloat162 b3 = __floats2bfloat162_rn(wr3.z, wr3.w);              \
        uint4 u0 = { *(uint32_t*)&a0, *(uint32_t*)&a1,                        \
                     *(uint32_t*)&a2, *(uint32_t*)&a3 };                      \
        uint4 u1 = { *(uint32_t*)&b0, *(uint32_t*)&b1,                        \
                     *(uint32_t*)&b2, *(uint32_t*)&b3 };                      \
        *(uint4*)(smem + (bufb) + sts0) = u0;                                 \
        *(uint4*)(smem + (bufb) + sts1) = u1;                                 \
    } while (0)

    // ---- prologue: X stages 0,1 in flight; W chunk0 -> buf0; chunk1 -> regs
    ISSUE_X(0); CP_COMMIT();
    ISSUE_X(1); CP_COMMIT();
    LDG_W(0); CVT_W(SM_W); LDG_W(1);

    float acc[4][4][4];
    #pragma unroll
    for (int mi = 0; mi < 4; ++mi)
        #pragma unroll
        for (int ni = 0; ni < 4; ++ni)
            #pragma unroll
            for (int j = 0; j < 4; ++j) acc[mi][ni][j] = 0.f;

    const uint32_t swz      = (lane & 7) << 4;
    const uint32_t xrowbase = (wm * 64 + (lane & 15)) * 128;
    const uint32_t kxA      = (lane >> 4) << 4;
    const uint32_t browbase = (wn * 32 + (lane & 7) + ((lane >> 4) << 3)) * 128;
    const uint32_t kxB      = ((lane >> 3) & 1) << 4;

    for (int kc = 0; kc < 8; ++kc) {
        CP_WAIT1();                 // X stage kc complete (kc+1 may be pending)
        __syncthreads();            // all warps done with stage kc-1 & W bufs
        if (kc < 6) { ISSUE_X(kc + 2); CP_COMMIT(); }   // slot (kc-1)%3: free

        const uint32_t xch = sb + SM_X + (kc % 3) * 32768 + xrowbase;
        const uint32_t wst = sb + SM_W + ((kc & 1) << 14) + browbase;
        #pragma unroll
        for (int ks = 0; ks < 4; ++ks) {
            uint32_t a[4][4], bq[2][4];
            const uint32_t ka = (uint32_t)(ks * 32 + kxA) ^ swz;
            const uint32_t kb = (uint32_t)(ks * 32 + kxB) ^ swz;
            #pragma unroll
            for (int mi = 0; mi < 4; ++mi) LDSM4(a[mi], xch + mi * 2048 + ka);
            #pragma unroll
            for (int nb = 0; nb < 2; ++nb) LDSM4(bq[nb], wst + nb * 2048 + kb);
            #pragma unroll
            for (int mi = 0; mi < 4; ++mi)
                #pragma unroll
                for (int nb = 0; nb < 2; ++nb) {
                    mma16816(acc[mi][2 * nb],     a[mi], &bq[nb][0]);
                    mma16816(acc[mi][2 * nb + 1], a[mi], &bq[nb][2]);
                }
        }

        // convert staged chunk kc+1 into buf (kc+1)&1 (last read at kc-1,
        // all warps past this iteration's barrier), then stage chunk kc+2.
        if (kc < 7) {
            CVT_W(SM_W + (((kc + 1) & 1) << 14));
            if (kc < 6) LDG_W(kc + 2);
        }
    }

    // ---- winv: quad-reduce per-thread sumsq (lanes 4c..4c+3 share class) --
    __syncthreads();
    float* winv_s = (float*)(smem + SM_WI);
    {
        float v = ss;
        v += __shfl_xor_sync(0xFFFFFFFFu, v, 1);
        v += __shfl_xor_sync(0xFFFFFFFFu, v, 2);
        if (q == 0) winv_s[wc] = ok ? rsqrtf(fmaxf(v, 1e-24f)) : 0.f;
    }
    __syncthreads();

    // ---- epilogue: cos = acc * winv; rowsum exp(64*cos - 64) ----
    float* racc = (float*)(smem + SM_W);   // buf0 free (last read kc=6)
    const int qq = lane & 3;
    const int g8 = lane >> 2;

    float2 wv[4];
    #pragma unroll
    for (int ni = 0; ni < 4; ++ni)
        wv[ni] = *(const float2*)&winv_s[wn * 32 + ni * 8 + 2 * qq];

    #pragma unroll
    for (int mi = 0; mi < 4; ++mi) {
        #pragma unroll
        for (int h = 0; h < 2; ++h) {
            const int lrow = wm * 64 + mi * 16 + g8 + 8 * h;
            const int grow = mt * 256 + lrow;
            const int yv   = y[grow];
            float rs = 0.f;
            #pragma unroll
            for (int ni = 0; ni < 4; ++ni) {
                const int cb = c0 + wn * 32 + ni * 8 + 2 * qq;
                float cv0 = acc[mi][ni][2 * h + 0] * wv[ni].x;
                float cv1 = acc[mi][ni][2 * h + 1] * wv[ni].y;
                if (cb == yv)     g_tgt[grow] = cv0;
                if (cb + 1 == yv) g_tgt[grow] = cv1;
                float e0 = __expf(fmaf(cv0, 64.f, -64.f));
                float e1 = __expf(fmaf(cv1, 64.f, -64.f));
                if (cb < NUM_C)     rs += e0;
                if (cb + 1 < NUM_C) rs += e1;
            }
            rs += __shfl_xor_sync(0xFFFFFFFFu, rs, 1);
            rs += __shfl_xor_sync(0xFFFFFFFFu, rs, 2);
            if (qq == 0) racc[lrow * 4 + wn] = rs;
        }
    }
    __syncthreads();
    if (tid < 256) {
        float s = racc[tid * 4 + 0] + racc[tid * 4 + 1]
                + racc[tid * 4 + 2] + racc[tid * 4 + 3];
        g_partial[(size_t)(mt * 256 + tid) * NCHP + cch] = s;
    }
    #undef ISSUE_X
    #undef LDG_W
    #undef CVT_W
}

// ---------------------------------------------------------------------------
__global__ void k_final1(float* __restrict__ nll_out) {
    __shared__ float red[8];
    const int row = blockIdx.x;
    const int t   = threadIdx.x;
    float s = 0.f;
    for (int c = t; c < NCCH; c += 256)
        s += g_partial[(size_t)row * NCHP + c];
    #pragma unroll
    for (int o = 16; o; o >>= 1) s += __shfl_xor_sync(0xFFFFFFFFu, s, o);
    if ((t & 31) == 0) red[t >> 5] = s;
    __syncthreads();
    if (t == 0) {
        float S = 0.f;
        #pragma unroll
        for (int k = 0; k < 8; ++k) S += red[k];
        float ct  = g_tgt[row];
        float sn  = sqrtf(fmaxf(1.f - ct * ct, 0.f));
        float cwm = ct * COS_M - sn * SIN_M;
        float phi = (ct > THv) ? cwm : (ct - MMRG);
        float Sp  = S - __expf(fmaf(ct, 64.f, -64.f)) + __expf(fmaf(phi, 64.f, -64.f));
        nll_out[row] = 64.f + logf(Sp) - 64.f * phi;
    }
}

__global__ void k_final2(float* __restrict__ out) {
    __shared__ float red[NB];
    const int t = threadIdx.x;
    red[t] = g_nll[t];
    __syncthreads();
    #pragma unroll
    for (int st = 256; st; st >>= 1) {
        if (t < st) red[t] += red[t + st];
        __syncthreads();
    }
    if (t == 0) out[0] = red[0] / (float)NB;
}

// ---------------------------------------------------------------------------
extern "C" void kernel_launch(void* const* d_in, const int* in_sizes, int n_in,
                              void* d_out, int out_size) {
    const float* x = (const float*)d_in[0];
    const int*   y = (const int*)d_in[1];
    const float* w = (const float*)d_in[2];
    float* out = (float*)d_out;

    cudaFuncSetAttribute(k_main, cudaFuncAttributeMaxDynamicSharedMemorySize,
                         (int)SMEM_BYTES);

    float* d_nll;
    cudaGetSymbolAddress((void**)&d_nll, g_nll);

    k_norm_x<<<64, 256>>>(x);
    k_main<<<dim3(2, NCCH), 512, SMEM_BYTES>>>(w, y);
    k_final1<<<NB, 256>>>(d_nll);
    k_final2<<<1, NB>>>(out);
}

// round 8
// speedup vs baseline: 1.3387x; 1.0441x over previous
#include <cuda_runtime.h>
#include <cuda_bf16.h>
#include <cstdint>

// ---------------------------------------------------------------------------
// ArcFace loss on GB300 (sm_103a). mma.sync pipeline (tcgen05 rejected by the
// harness's compute_103 virtual target).
//   k_prep  : W fp32 -> bf16 (g_wn) + inv-norms (g_winv); X normalized bf16.
//   k_main  : 3128 CTAs (4 M-tiles x 782 chunks of 128 classes), 256 threads,
//             2 CTAs/SM. X and W both streamed as 128x64 bf16 stages via a
//             3-slot cp.async pipeline (one commit group per k-chunk).
//             64x32 warp tiles, ldmatrix.x4 + HMMA; fused exp(64*cos-64)
//             row sums (fixed-max LSE trick).
//   k_final : per-row combine of 782 partials + margin + nll; last block
//             reduces the 512 nll values to the mean (counter pattern).
// ---------------------------------------------------------------------------

namespace {
constexpr int NUM_C = 100000;
constexpr int DIM   = 512;
constexpr int NB    = 512;

constexpr int NPC   = 128;                        // classes per CTA
constexpr int NCCH  = (NUM_C + NPC - 1) / NPC;    // 782
constexpr int NCHP  = 784;                        // padded partial stride
constexpr int CPAD  = NCCH * NPC;                 // 100096

constexpr int SM_X  = 0;                 // 3 stages * 16384 = 49152
constexpr int SM_W  = 49152;             // 3 stages * 16384 = 49152
constexpr size_t SMEM_BYTES = 98304;     // 2 CTAs/SM -> 192KB <= 228KB

constexpr float COS_M = 0.8775825618903728f;   // cos(0.5)
constexpr float SIN_M = 0.479425538604203f;    // sin(0.5)
constexpr float THv   = -0.8775825618903728f;  // -cos(m)
constexpr float MMRG  = 0.2397127693021015f;   // sin(m)*m
} // namespace

__device__ __align__(16) __nv_bfloat16 g_xn[NB * DIM];
__device__ __align__(16) __nv_bfloat16 g_wn[(size_t)CPAD * DIM];
__device__ float g_winv[CPAD];
__device__ float g_tgt[NB];
__device__ float g_partial[(size_t)NB * NCHP];   // [row][chunk]
__device__ float g_nll[NB];
__device__ unsigned g_cnt = 0;

// ---------------------------------------------------------------------------
__device__ __forceinline__ uint32_t smem_u32(const void* p) {
    uint32_t a;
    asm("{ .reg .u64 t; cvta.to.shared.u64 t, %1; cvt.u32.u64 %0, t; }"
        : "=r"(a) : "l"(p));
    return a;
}
#define CP_ASYNC16(dst, src) \
    asm volatile("cp.async.cg.shared.global [%0], [%1], 16;" \
                 :: "r"(dst), "l"(src) : "memory")
#define CP_COMMIT() asm volatile("cp.async.commit_group;" ::: "memory")
#define CP_WAIT1()  asm volatile("cp.async.wait_group 1;" ::: "memory")

#define LDSM4(r, addr) \
    asm volatile("ldmatrix.sync.aligned.m8n8.x4.shared.b16 {%0,%1,%2,%3}, [%4];" \
                 : "=r"((r)[0]), "=r"((r)[1]), "=r"((r)[2]), "=r"((r)[3])        \
                 : "r"(addr))

__device__ __forceinline__ void mma16816(float* c, const uint32_t* a,
                                         const uint32_t* b) {
    asm volatile(
        "mma.sync.aligned.m16n8k16.row.col.f32.bf16.bf16.f32 "
        "{%0,%1,%2,%3}, {%4,%5,%6,%7}, {%8,%9}, {%0,%1,%2,%3};\n"
        : "+f"(c[0]), "+f"(c[1]), "+f"(c[2]), "+f"(c[3])
        : "r"(a[0]), "r"(a[1]), "r"(a[2]), "r"(a[3]), "r"(b[0]), "r"(b[1]));
}

// ---------------------------------------------------------------------------
// Prep: blocks 0..1563 convert 64 W rows each (zero-pad past NUM_C);
//       blocks 1564..1565 normalize 256 X rows each.
// ---------------------------------------------------------------------------
__global__ void k_prep(const float* __restrict__ x, const float* __restrict__ w) {
    const int bid  = blockIdx.x;
    const int wid  = threadIdx.x >> 5;
    const int lane = threadIdx.x & 31;

    if (bid < CPAD / 64) {
        const int base = bid * 64 + wid * 8;
        #pragma unroll
        for (int r = 0; r < 8; ++r) {
            const int row = base + r;
            float4 a0, a1, a2, a3;
            float ss = 0.f;
            if (row < NUM_C) {
                const float4* src = (const float4*)(w + (size_t)row * DIM);
                a0 = src[2 * lane];
                a1 = src[2 * lane + 1];
                a2 = src[2 * lane + 64];
                a3 = src[2 * lane + 65];
                ss = a0.x * a0.x + a0.y * a0.y + a0.z * a0.z + a0.w * a0.w
                   + a1.x * a1.x + a1.y * a1.y + a1.z * a1.z + a1.w * a1.w
                   + a2.x * a2.x + a2.y * a2.y + a2.z * a2.z + a2.w * a2.w
                   + a3.x * a3.x + a3.y * a3.y + a3.z * a3.z + a3.w * a3.w;
            } else {
                a0 = a1 = a2 = a3 = make_float4(0.f, 0.f, 0.f, 0.f);
            }
            #pragma unroll
            for (int o = 16; o; o >>= 1) ss += __shfl_xor_sync(0xFFFFFFFFu, ss, o);

            uint4* dst = (uint4*)(g_wn + (size_t)row * DIM);
            {
                __nv_bfloat162 p0 = __floats2bfloat162_rn(a0.x, a0.y);
                __nv_bfloat162 p1 = __floats2bfloat162_rn(a0.z, a0.w);
                __nv_bfloat162 p2 = __floats2bfloat162_rn(a1.x, a1.y);
                __nv_bfloat162 p3 = __floats2bfloat162_rn(a1.z, a1.w);
                uint4 u = { *(uint32_t*)&p0, *(uint32_t*)&p1,
                            *(uint32_t*)&p2, *(uint32_t*)&p3 };
                dst[lane] = u;
            }
            {
                __nv_bfloat162 p0 = __floats2bfloat162_rn(a2.x, a2.y);
                __nv_bfloat162 p1 = __floats2bfloat162_rn(a2.z, a2.w);
                __nv_bfloat162 p2 = __floats2bfloat162_rn(a3.x, a3.y);
                __nv_bfloat162 p3 = __floats2bfloat162_rn(a3.z, a3.w);
                uint4 u = { *(uint32_t*)&p0, *(uint32_t*)&p1,
                            *(uint32_t*)&p2, *(uint32_t*)&p3 };
                dst[lane + 32] = u;
            }
            if (lane == 0)
                g_winv[row] = (row < NUM_C) ? rsqrtf(fmaxf(ss, 1e-24f)) : 0.f;
        }
    } else {
        const int xb = (bid - CPAD / 64) * 256 + wid * 32;
        for (int r = 0; r < 32; ++r) {
            const int row = xb + r;
            const float4* xr = (const float4*)(x + (size_t)row * DIM);
            float4 v[4];
            float s = 0.f;
            #pragma unroll
            for (int j = 0; j < 4; ++j) {
                v[j] = xr[lane + 32 * j];
                s += v[j].x * v[j].x + v[j].y * v[j].y
                   + v[j].z * v[j].z + v[j].w * v[j].w;
            }
            #pragma unroll
            for (int o = 16; o; o >>= 1) s += __shfl_xor_sync(0xFFFFFFFFu, s, o);
            float inv = rsqrtf(fmaxf(s, 1e-24f));
            uint2* dst = (uint2*)(g_xn + (size_t)row * DIM);
            #pragma unroll
            for (int j = 0; j < 4; ++j) {
                __nv_bfloat162 lo = __floats2bfloat162_rn(v[j].x * inv, v[j].y * inv);
                __nv_bfloat162 hi = __floats2bfloat162_rn(v[j].z * inv, v[j].w * inv);
                uint2 u;
                u.x = *(uint32_t*)&lo;
                u.y = *(uint32_t*)&hi;
                dst[lane + 32 * j] = u;
            }
        }
    }
}

// ---------------------------------------------------------------------------
__global__ void __launch_bounds__(256, 2)
k_main(const int* __restrict__ y) {
    extern __shared__ char smem[];
    const uint32_t sb = smem_u32(smem);
    const int tid  = threadIdx.x;
    const int wid  = tid >> 5;
    const int lane = tid & 31;
    const int mt   = blockIdx.x;           // 0..3 (128-row tile)
    const int cch  = blockIdx.y;           // 0..781
    const int c0   = cch * NPC;
    const int wm   = wid >> 2;             // 0..1  (64-row half)
    const int wn   = wid & 3;              // 0..3  (32-col slice)

    const char* xsrc = (const char*)g_xn + (size_t)mt * 128 * DIM * 2;
    const char* wsrc = (const char*)g_wn + (size_t)c0 * DIM * 2;

    // X and W stages share geometry: 128 rows x 64 bf16 = 16KB, SW swizzled.
    #define ISSUE_XW(kc) do {                                                 \
        uint32_t xs_ = sb + SM_X + ((kc) % 3) * 16384;                        \
        uint32_t ws_ = sb + SM_W + ((kc) % 3) * 16384;                        \
        _Pragma("unroll")                                                     \
        for (int i = 0; i < 4; ++i) {                                         \
            int li = tid + 256 * i;                                           \
            int row = li >> 3, seg = li & 7;                                  \
            uint32_t off = row * 128 + ((seg * 16) ^ ((row & 7) << 4));       \
            size_t goff = ((size_t)row * DIM + (kc) * 64 + seg * 8) * 2;      \
            CP_ASYNC16(xs_ + off, xsrc + goff);                               \
            CP_ASYNC16(ws_ + off, wsrc + goff);                               \
        }                                                                     \
    } while (0)

    ISSUE_XW(0); CP_COMMIT();
    ISSUE_XW(1); CP_COMMIT();

    float acc[4][4][4];
    #pragma unroll
    for (int mi = 0; mi < 4; ++mi)
        #pragma unroll
        for (int ni = 0; ni < 4; ++ni)
            #pragma unroll
            for (int j = 0; j < 4; ++j) acc[mi][ni][j] = 0.f;

    const uint32_t swz      = (lane & 7) << 4;
    const uint32_t xrowbase = (wm * 64 + (lane & 15)) * 128;
    const uint32_t kxA      = (lane >> 4) << 4;
    const uint32_t browbase = (wn * 32 + (lane & 7) + ((lane >> 4) << 3)) * 128;
    const uint32_t kxB      = ((lane >> 3) & 1) << 4;

    for (int kc = 0; kc < 8; ++kc) {
        CP_WAIT1();                 // chunk kc complete (kc+1 may be pending)
        __syncthreads();            // stage (kc+2)%3 = (kc-1)%3 is free
        if (kc < 6) ISSUE_XW(kc + 2);
        CP_COMMIT();                // unconditional: keeps group count aligned

        const uint32_t xch = sb + SM_X + (kc % 3) * 16384 + xrowbase;
        const uint32_t wst = sb + SM_W + (kc % 3) * 16384 + browbase;
        #pragma unroll
        for (int ks = 0; ks < 4; ++ks) {
            uint32_t a[4][4], bq[2][4];
            const uint32_t ka = (uint32_t)(ks * 32 + kxA) ^ swz;
            const uint32_t kb = (uint32_t)(ks * 32 + kxB) ^ swz;
            #pragma unroll
            for (int mi = 0; mi < 4; ++mi) LDSM4(a[mi], xch + mi * 2048 + ka);
            #pragma unroll
            for (int nb = 0; nb < 2; ++nb) LDSM4(bq[nb], wst + nb * 2048 + kb);
            #pragma unroll
            for (int mi = 0; mi < 4; ++mi)
                #pragma unroll
                for (int nb = 0; nb < 2; ++nb) {
                    mma16816(acc[mi][2 * nb],     a[mi], &bq[nb][0]);
                    mma16816(acc[mi][2 * nb + 1], a[mi], &bq[nb][2]);
                }
        }
    }

    // ---- epilogue: cos = acc * winv; rowsum exp(64*cos - 64) ----
    // racc overlays X stage 0 (16KB region; last consumed at kc=6, and all
    // warps are past the kc=7 top barrier which follows that consume).
    float* racc = (float*)(smem + SM_X);
    const int qq = lane & 3;
    const int g8 = lane >> 2;

    float2 wv[4];
    #pragma unroll
    for (int ni = 0; ni < 4; ++ni)
        wv[ni] = *(const float2*)&g_winv[c0 + wn * 32 + ni * 8 + 2 * qq];

    #pragma unroll
    for (int mi = 0; mi < 4; ++mi) {
        #pragma unroll
        for (int h = 0; h < 2; ++h) {
            const int lrow = wm * 64 + mi * 16 + g8 + 8 * h;
            const int grow = mt * 128 + lrow;
            const int yv   = y[grow];
            float rs = 0.f;
            #pragma unroll
            for (int ni = 0; ni < 4; ++ni) {
                const int cb = c0 + wn * 32 + ni * 8 + 2 * qq;
                float cv0 = acc[mi][ni][2 * h + 0] * wv[ni].x;
                float cv1 = acc[mi][ni][2 * h + 1] * wv[ni].y;
                if (cb == yv)     g_tgt[grow] = cv0;
                if (cb + 1 == yv) g_tgt[grow] = cv1;
                float e0 = __expf(fmaf(cv0, 64.f, -64.f));
                float e1 = __expf(fmaf(cv1, 64.f, -64.f));
                if (cb < NUM_C)     rs += e0;
                if (cb + 1 < NUM_C) rs += e1;
            }
            rs += __shfl_xor_sync(0xFFFFFFFFu, rs, 1);
            rs += __shfl_xor_sync(0xFFFFFFFFu, rs, 2);
            if (qq == 0) racc[lrow * 4 + wn] = rs;
        }
    }
    __syncthreads();
    if (tid < 128) {
        float s = racc[tid * 4 + 0] + racc[tid * 4 + 1]
                + racc[tid * 4 + 2] + racc[tid * 4 + 3];
        g_partial[(size_t)(mt * 128 + tid) * NCHP + cch] = s;
    }
    #undef ISSUE_XW
}

// ---------------------------------------------------------------------------
// k_final: one block per row (512 blocks x 256 threads). Each block reduces
// its row's 782 partials + margin -> g_nll[row]. The last block to finish
// (counter) reduces all 512 nll values in a fixed deterministic order.
__global__ void k_final(float* __restrict__ out) {
    __shared__ float red[8];
    __shared__ float sred[256];
    __shared__ int slast;
    const int row = blockIdx.x;
    const int t   = threadIdx.x;

    float s = 0.f;
    for (int c = t; c < NCCH; c += 256)
        s += g_partial[(size_t)row * NCHP + c];
    #pragma unroll
    for (int o = 16; o; o >>= 1) s += __shfl_xor_sync(0xFFFFFFFFu, s, o);
    if ((t & 31) == 0) red[t >> 5] = s;
    __syncthreads();
    if (t == 0) {
        float S = 0.f;
        #pragma unroll
        for (int k = 0; k < 8; ++k) S += red[k];
        float ct  = g_tgt[row];
        float sn  = sqrtf(fmaxf(1.f - ct * ct, 0.f));
        float cwm = ct * COS_M - sn * SIN_M;
        float phi = (ct > THv) ? cwm : (ct - MMRG);
        float Sp  = S - __expf(fmaf(ct, 64.f, -64.f)) + __expf(fmaf(phi, 64.f, -64.f));
        g_nll[row] = 64.f + logf(Sp) - 64.f * phi;
        __threadfence();
        unsigned v = atomicAdd(&g_cnt, 1u);
        slast = (v == (unsigned)(gridDim.x - 1));
    }
    __syncthreads();
    if (slast) {
        __threadfence();
        float v = g_nll[t] + g_nll[t + 256];
        sred[t] = v;
        __syncthreads();
        #pragma unroll
        for (int st = 128; st; st >>= 1) {
            if (t < st) sred[t] += sred[t + st];
            __syncthreads();
        }
        if (t == 0) { out[0] = sred[0] / (float)NB; g_cnt = 0; }
    }
}

// ---------------------------------------------------------------------------
extern "C" void kernel_launch(void* const* d_in, const int* in_sizes, int n_in,
                              void* d_out, int out_size) {
    const float* x = (const float*)d_in[0];
    const int*   y = (const int*)d_in[1];
    const float* w = (const float*)d_in[2];
    float* out = (float*)d_out;

    cudaFuncSetAttribute(k_main, cudaFuncAttributeMaxDynamicSharedMemorySize,
                         (int)SMEM_BYTES);

    k_prep<<<CPAD / 64 + 2, 256>>>(x, w);
    k_main<<<dim3(4, NCCH), 256, SMEM_BYTES>>>(y);
    k_final<<<NB, 256>>>(out);
}

// round 9
// speedup vs baseline: 1.3643x; 1.0191x over previous
#include <cuda_runtime.h>
#include <cuda_bf16.h>
#include <cstdint>

// ---------------------------------------------------------------------------
// ArcFace loss on GB300 (sm_103a). mma.sync pipeline (tcgen05 rejected by the
// harness's compute_103 virtual target).
//   k_prep  : W rows L2-normalized fp32 -> bf16 (g_wn); X rows likewise
//             (g_xn). Row pairs processed together for 2x memory-level
//             parallelism. W is read from DRAM exactly once.
//   k_main  : 3128 CTAs (4 M-tiles x 782 chunks of 128 classes), 256 threads,
//             2 CTAs/SM. X and W streamed as 128x64 bf16 stages via a 3-slot
//             cp.async pipeline. 64x32 warp tiles, ldmatrix.x4 + HMMA;
//             cos == accumulator (W pre-normalized); fused exp(64*cos-64)
//             row sums (fixed-max LSE trick).
//   k_final : per-row combine of 782 partials + margin + nll; last block
//             (counter) reduces 512 nll values to the mean.
// ---------------------------------------------------------------------------

namespace {
constexpr int NUM_C = 100000;
constexpr int DIM   = 512;
constexpr int NB    = 512;

constexpr int NPC   = 128;                        // classes per CTA
constexpr int NCCH  = (NUM_C + NPC - 1) / NPC;    // 782
constexpr int NCHP  = 784;                        // padded partial stride
constexpr int CPAD  = NCCH * NPC;                 // 100096

constexpr int SM_X  = 0;                 // 3 stages * 16384 = 49152
constexpr int SM_W  = 49152;             // 3 stages * 16384 = 49152
constexpr size_t SMEM_BYTES = 98304;     // 2 CTAs/SM -> 192KB

constexpr float COS_M = 0.8775825618903728f;   // cos(0.5)
constexpr float SIN_M = 0.479425538604203f;    // sin(0.5)
constexpr float THv   = -0.8775825618903728f;  // -cos(m)
constexpr float MMRG  = 0.2397127693021015f;   // sin(m)*m
} // namespace

__device__ __align__(16) __nv_bfloat16 g_xn[NB * DIM];
__device__ __align__(16) __nv_bfloat16 g_wn[(size_t)CPAD * DIM];
__device__ float g_tgt[NB];
__device__ float g_partial[(size_t)NB * NCHP];   // [row][chunk]
__device__ float g_nll[NB];
__device__ unsigned g_cnt = 0;

// ---------------------------------------------------------------------------
__device__ __forceinline__ uint32_t smem_u32(const void* p) {
    uint32_t a;
    asm("{ .reg .u64 t; cvta.to.shared.u64 t, %1; cvt.u32.u64 %0, t; }"
        : "=r"(a) : "l"(p));
    return a;
}
#define CP_ASYNC16(dst, src) \
    asm volatile("cp.async.cg.shared.global [%0], [%1], 16;" \
                 :: "r"(dst), "l"(src) : "memory")
#define CP_COMMIT() asm volatile("cp.async.commit_group;" ::: "memory")
#define CP_WAIT1()  asm volatile("cp.async.wait_group 1;" ::: "memory")

#define LDSM4(r, addr) \
    asm volatile("ldmatrix.sync.aligned.m8n8.x4.shared.b16 {%0,%1,%2,%3}, [%4];" \
                 : "=r"((r)[0]), "=r"((r)[1]), "=r"((r)[2]), "=r"((r)[3])        \
                 : "r"(addr))

__device__ __forceinline__ void mma16816(float* c, const uint32_t* a,
                                         const uint32_t* b) {
    asm volatile(
        "mma.sync.aligned.m16n8k16.row.col.f32.bf16.bf16.f32 "
        "{%0,%1,%2,%3}, {%4,%5,%6,%7}, {%8,%9}, {%0,%1,%2,%3};\n"
        : "+f"(c[0]), "+f"(c[1]), "+f"(c[2]), "+f"(c[3])
        : "r"(a[0]), "r"(a[1]), "r"(a[2]), "r"(a[3]), "r"(b[0]), "r"(b[1]));
}

// normalize+convert one row's 4 float4 (per-lane slice) and store 2x16B
__device__ __forceinline__ void norm_store(float4 v0, float4 v1, float4 v2,
                                           float4 v3, float inv,
                                           uint4* dst, int lane) {
    __nv_bfloat162 p0 = __floats2bfloat162_rn(v0.x * inv, v0.y * inv);
    __nv_bfloat162 p1 = __floats2bfloat162_rn(v0.z * inv, v0.w * inv);
    __nv_bfloat162 p2 = __floats2bfloat162_rn(v1.x * inv, v1.y * inv);
    __nv_bfloat162 p3 = __floats2bfloat162_rn(v1.z * inv, v1.w * inv);
    uint4 u0 = { *(uint32_t*)&p0, *(uint32_t*)&p1,
                 *(uint32_t*)&p2, *(uint32_t*)&p3 };
    __nv_bfloat162 q0 = __floats2bfloat162_rn(v2.x * inv, v2.y * inv);
    __nv_bfloat162 q1 = __floats2bfloat162_rn(v2.z * inv, v2.w * inv);
    __nv_bfloat162 q2 = __floats2bfloat162_rn(v3.x * inv, v3.y * inv);
    __nv_bfloat162 q3 = __floats2bfloat162_rn(v3.z * inv, v3.w * inv);
    uint4 u1 = { *(uint32_t*)&q0, *(uint32_t*)&q1,
                 *(uint32_t*)&q2, *(uint32_t*)&q3 };
    dst[lane]      = u0;
    dst[lane + 32] = u1;
}

// ---------------------------------------------------------------------------
// Prep: blocks 0..1563 normalize 64 W rows each (zero past NUM_C);
//       blocks 1564..1565 normalize 256 X rows each. Rows in pairs for MLP.
// ---------------------------------------------------------------------------
__global__ void k_prep(const float* __restrict__ x, const float* __restrict__ w) {
    const int bid  = blockIdx.x;
    const int wid  = threadIdx.x >> 5;
    const int lane = threadIdx.x & 31;

    const bool is_w = (bid < CPAD / 64);
    const float* src_mat = is_w ? w : x;
    const int nrows      = is_w ? NUM_C : NB;
    __nv_bfloat16* dst_mat = is_w ? g_wn : g_xn;
    const int base = is_w ? (bid * 64 + wid * 8)
                          : ((bid - CPAD / 64) * 256 + wid * 32);
    const int per  = is_w ? 8 : 32;

    for (int rp = 0; rp < per; rp += 2) {
        const int r0 = base + rp, r1 = r0 + 1;
        float4 a0, a1, a2, a3, b0, b1, b2, b3;
        float s0 = 0.f, s1 = 0.f;
        const bool ok0 = r0 < nrows, ok1 = r1 < nrows;
        if (ok0) {
            const float4* p = (const float4*)(src_mat + (size_t)r0 * DIM);
            a0 = p[2 * lane]; a1 = p[2 * lane + 1];
            a2 = p[2 * lane + 64]; a3 = p[2 * lane + 65];
        } else a0 = a1 = a2 = a3 = make_float4(0.f, 0.f, 0.f, 0.f);
        if (ok1) {
            const float4* p = (const float4*)(src_mat + (size_t)r1 * DIM);
            b0 = p[2 * lane]; b1 = p[2 * lane + 1];
            b2 = p[2 * lane + 64]; b3 = p[2 * lane + 65];
        } else b0 = b1 = b2 = b3 = make_float4(0.f, 0.f, 0.f, 0.f);

        s0 = a0.x * a0.x + a0.y * a0.y + a0.z * a0.z + a0.w * a0.w
           + a1.x * a1.x + a1.y * a1.y + a1.z * a1.z + a1.w * a1.w
           + a2.x * a2.x + a2.y * a2.y + a2.z * a2.z + a2.w * a2.w
           + a3.x * a3.x + a3.y * a3.y + a3.z * a3.z + a3.w * a3.w;
        s1 = b0.x * b0.x + b0.y * b0.y + b0.z * b0.z + b0.w * b0.w
           + b1.x * b1.x + b1.y * b1.y + b1.z * b1.z + b1.w * b1.w
           + b2.x * b2.x + b2.y * b2.y + b2.z * b2.z + b2.w * b2.w
           + b3.x * b3.x + b3.y * b3.y + b3.z * b3.z + b3.w * b3.w;
        #pragma unroll
        for (int o = 16; o; o >>= 1) {
            s0 += __shfl_xor_sync(0xFFFFFFFFu, s0, o);
            s1 += __shfl_xor_sync(0xFFFFFFFFu, s1, o);
        }
        const float inv0 = ok0 ? rsqrtf(fmaxf(s0, 1e-24f)) : 0.f;
        const float inv1 = ok1 ? rsqrtf(fmaxf(s1, 1e-24f)) : 0.f;
        norm_store(a0, a1, a2, a3, inv0,
                   (uint4*)(dst_mat + (size_t)r0 * DIM), lane);
        if (is_w || ok1)
            norm_store(b0, b1, b2, b3, inv1,
                       (uint4*)(dst_mat + (size_t)r1 * DIM), lane);
    }
}

// ---------------------------------------------------------------------------
__global__ void __launch_bounds__(256, 2)
k_main(const int* __restrict__ y) {
    extern __shared__ char smem[];
    const uint32_t sb = smem_u32(smem);
    const int tid  = threadIdx.x;
    const int wid  = tid >> 5;
    const int lane = tid & 31;
    const int mt   = blockIdx.x;           // 0..3 (128-row tile)
    const int cch  = blockIdx.y;           // 0..781
    const int c0   = cch * NPC;
    const int wm   = wid >> 2;             // 0..1  (64-row half)
    const int wn   = wid & 3;              // 0..3  (32-col slice)

    const char* xsrc = (const char*)g_xn + (size_t)mt * 128 * DIM * 2;
    const char* wsrc = (const char*)g_wn + (size_t)c0 * DIM * 2;

    #define ISSUE_XW(kc) do {                                                 \
        uint32_t xs_ = sb + SM_X + ((kc) % 3) * 16384;                        \
        uint32_t ws_ = sb + SM_W + ((kc) % 3) * 16384;                        \
        _Pragma("unroll")                                                     \
        for (int i = 0; i < 4; ++i) {                                         \
            int li = tid + 256 * i;                                           \
            int row = li >> 3, seg = li & 7;                                  \
            uint32_t off = row * 128 + ((seg * 16) ^ ((row & 7) << 4));       \
            size_t goff = ((size_t)row * DIM + (kc) * 64 + seg * 8) * 2;      \
            CP_ASYNC16(xs_ + off, xsrc + goff);                               \
            CP_ASYNC16(ws_ + off, wsrc + goff);                               \
        }                                                                     \
    } while (0)

    ISSUE_XW(0); CP_COMMIT();
    ISSUE_XW(1); CP_COMMIT();

    float acc[4][4][4];
    #pragma unroll
    for (int mi = 0; mi < 4; ++mi)
        #pragma unroll
        for (int ni = 0; ni < 4; ++ni)
            #pragma unroll
            for (int j = 0; j < 4; ++j) acc[mi][ni][j] = 0.f;

    const uint32_t swz      = (lane & 7) << 4;
    const uint32_t xrowbase = (wm * 64 + (lane & 15)) * 128;
    const uint32_t kxA      = (lane >> 4) << 4;
    const uint32_t browbase = (wn * 32 + (lane & 7) + ((lane >> 4) << 3)) * 128;
    const uint32_t kxB      = ((lane >> 3) & 1) << 4;

    for (int kc = 0; kc < 8; ++kc) {
        CP_WAIT1();
        __syncthreads();
        if (kc < 6) ISSUE_XW(kc + 2);
        CP_COMMIT();

        const uint32_t xch = sb + SM_X + (kc % 3) * 16384 + xrowbase;
        const uint32_t wst = sb + SM_W + (kc % 3) * 16384 + browbase;
        #pragma unroll
        for (int ks = 0; ks < 4; ++ks) {
            uint32_t a[4][4], bq[2][4];
            const uint32_t ka = (uint32_t)(ks * 32 + kxA) ^ swz;
            const uint32_t kb = (uint32_t)(ks * 32 + kxB) ^ swz;
            #pragma unroll
            for (int mi = 0; mi < 4; ++mi) LDSM4(a[mi], xch + mi * 2048 + ka);
            #pragma unroll
            for (int nb = 0; nb < 2; ++nb) LDSM4(bq[nb], wst + nb * 2048 + kb);
            #pragma unroll
            for (int mi = 0; mi < 4; ++mi)
                #pragma unroll
                for (int nb = 0; nb < 2; ++nb) {
                    mma16816(acc[mi][2 * nb],     a[mi], &bq[nb][0]);
                    mma16816(acc[mi][2 * nb + 1], a[mi], &bq[nb][2]);
                }
        }
    }

    // ---- epilogue: cos == acc (W pre-normalized); rowsum exp(64*cos-64) ---
    float* racc = (float*)(smem + SM_X);
    const int qq = lane & 3;
    const int g8 = lane >> 2;

    #pragma unroll
    for (int mi = 0; mi < 4; ++mi) {
        #pragma unroll
        for (int h = 0; h < 2; ++h) {
            const int lrow = wm * 64 + mi * 16 + g8 + 8 * h;
            const int grow = mt * 128 + lrow;
            const int yv   = y[grow];
            float rs = 0.f;
            #pragma unroll
            for (int ni = 0; ni < 4; ++ni) {
                const int cb = c0 + wn * 32 + ni * 8 + 2 * qq;
                float cv0 = acc[mi][ni][2 * h + 0];
                float cv1 = acc[mi][ni][2 * h + 1];
                if (cb == yv)     g_tgt[grow] = cv0;
                if (cb + 1 == yv) g_tgt[grow] = cv1;
                float e0 = __expf(fmaf(cv0, 64.f, -64.f));
                float e1 = __expf(fmaf(cv1, 64.f, -64.f));
                if (cb < NUM_C)     rs += e0;
                if (cb + 1 < NUM_C) rs += e1;
            }
            rs += __shfl_xor_sync(0xFFFFFFFFu, rs, 1);
            rs += __shfl_xor_sync(0xFFFFFFFFu, rs, 2);
            if (qq == 0) racc[lrow * 4 + wn] = rs;
        }
    }
    __syncthreads();
    if (tid < 128) {
        float s = racc[tid * 4 + 0] + racc[tid * 4 + 1]
                + racc[tid * 4 + 2] + racc[tid * 4 + 3];
        g_partial[(size_t)(mt * 128 + tid) * NCHP + cch] = s;
    }
    #undef ISSUE_XW
}

// ---------------------------------------------------------------------------
__global__ void k_final(float* __restrict__ out) {
    __shared__ float red[8];
    __shared__ float sred[256];
    __shared__ int slast;
    const int row = blockIdx.x;
    const int t   = threadIdx.x;

    float s = 0.f;
    for (int c = t; c < NCCH; c += 256)
        s += g_partial[(size_t)row * NCHP + c];
    #pragma unroll
    for (int o = 16; o; o >>= 1) s += __shfl_xor_sync(0xFFFFFFFFu, s, o);
    if ((t & 31) == 0) red[t >> 5] = s;
    __syncthreads();
    if (t == 0) {
        float S = 0.f;
        #pragma unroll
        for (int k = 0; k < 8; ++k) S += red[k];
        float ct  = g_tgt[row];
        float sn  = sqrtf(fmaxf(1.f - ct * ct, 0.f));
        float cwm = ct * COS_M - sn * SIN_M;
        float phi = (ct > THv) ? cwm : (ct - MMRG);
        float Sp  = S - __expf(fmaf(ct, 64.f, -64.f)) + __expf(fmaf(phi, 64.f, -64.f));
        g_nll[row] = 64.f + logf(Sp) - 64.f * phi;
        __threadfence();
        unsigned v = atomicAdd(&g_cnt, 1u);
        slast = (v == (unsigned)(gridDim.x - 1));
    }
    __syncthreads();
    if (slast) {
        __threadfence();
        float v = g_nll[t] + g_nll[t + 256];
        sred[t] = v;
        __syncthreads();
        #pragma unroll
        for (int st = 128; st; st >>= 1) {
            if (t < st) sred[t] += sred[t + st];
            __syncthreads();
        }
        if (t == 0) { out[0] = sred[0] / (float)NB; g_cnt = 0; }
    }
}

// ---------------------------------------------------------------------------
extern "C" void kernel_launch(void* const* d_in, const int* in_sizes, int n_in,
                              void* d_out, int out_size) {
    const float* x = (const float*)d_in[0];
    const int*   y = (const int*)d_in[1];
    const float* w = (const float*)d_in[2];
    float* out = (float*)d_out;

    cudaFuncSetAttribute(k_main, cudaFuncAttributeMaxDynamicSharedMemorySize,
                         (int)SMEM_BYTES);

    k_prep<<<CPAD / 64 + 2, 256>>>(x, w);
    k_main<<<dim3(4, NCCH), 256, SMEM_BYTES>>>(y);
    k_final<<<NB, 256>>>(out);
}